// round 2
// baseline (speedup 1.0000x reference)
#include <cuda_runtime.h>
#include <cstdint>

#define NN 50000
#define NE 1600000
#define D  128
#define C  21

// Scratch in __device__ globals (no cudaMalloc allowed).
__device__ float g_Wc[2][D][C];        // fused Wsrc@Wcls, Wdst@Wcls
__device__ float g_cvec[C];            // b_fuse@Wcls + b_cls
__device__ float g_Asrc[NN][C];        // emb @ Wc[0] + cvec (bias folded)
__device__ float g_Adst[NN][C];        // emb @ Wc[1]
__device__ int   g_is64;               // 1 if edge_index delivered as int64

// --------------------------------------------------------------------------
// Kernel 0: detect edge_index dtype. If the buffer holds int32 indices, an
// int64 reinterpretation packs two random indices -> value >= 2^32 (whp).
// Deterministic for fixed input.
// --------------------------------------------------------------------------
__global__ void detect_dtype_kernel(const long long* __restrict__ ei) {
    if (threadIdx.x == 0 && blockIdx.x == 0) {
        bool ok64 = true;
        #pragma unroll
        for (int k = 0; k < 4; k++) {
            long long v = ei[k];
            if (v < 0 || v >= NN) ok64 = false;
        }
        g_is64 = ok64 ? 1 : 0;
    }
}

// --------------------------------------------------------------------------
// Kernel 1: fold the [D,D] fuse weights through the classifier -> [D,C].
// --------------------------------------------------------------------------
__global__ void fuse_weights_kernel(const float* __restrict__ Wsrc,
                                    const float* __restrict__ Wdst,
                                    const float* __restrict__ bfuse,
                                    const float* __restrict__ Wcls,
                                    const float* __restrict__ bcls) {
    int i = blockIdx.x * blockDim.x + threadIdx.x;
    if (i < 2 * D * C) {
        int which = i / (D * C);
        int rem   = i - which * (D * C);
        int r = rem / C;
        int c = rem - r * C;
        const float* W = which ? Wdst : Wsrc;
        float acc = 0.f;
        #pragma unroll 16
        for (int j = 0; j < D; j++)
            acc += W[r * D + j] * Wcls[j * C + c];
        g_Wc[which][r][c] = acc;
    } else if (i < 2 * D * C + C) {
        int c = i - 2 * D * C;
        float acc = bcls[c];
        for (int j = 0; j < D; j++)
            acc += bfuse[j] * Wcls[j * C + c];
        g_cvec[c] = acc;
    }
}

// --------------------------------------------------------------------------
// Kernel 2: per-node projection tables. Block = 32x8: tx=class, ty=node.
// Fused weights staged in shared (21.5 KB) + 8 node rows (4 KB).
// --------------------------------------------------------------------------
__global__ __launch_bounds__(256) void node_proj_kernel(const float* __restrict__ emb) {
    __shared__ float sW[2][D][C];
    __shared__ float sx[8][D];

    int tid = threadIdx.y * 32 + threadIdx.x;

    const float* gW = &g_Wc[0][0][0];
    for (int i = tid; i < 2 * D * C; i += 256)
        (&sW[0][0][0])[i] = gW[i];

    int node0 = blockIdx.x * 8;
    for (int i = tid; i < 8 * D; i += 256) {
        int n = node0 + (i >> 7);
        sx[i >> 7][i & 127] = (n < NN) ? emb[(size_t)n * D + (i & 127)] : 0.f;
    }
    __syncthreads();

    int c = threadIdx.x;
    int n = node0 + threadIdx.y;
    if (c < C && n < NN) {
        float a = 0.f, b = 0.f;
        #pragma unroll 8
        for (int k = 0; k < D; k++) {
            float x = sx[threadIdx.y][k];
            a += x * sW[0][k][c];
            b += x * sW[1][k][c];
        }
        g_Asrc[n][c] = a + g_cvec[c];
        g_Adst[n][c] = b;
    }
}

// --------------------------------------------------------------------------
// Kernel 3: per-edge gather + add. One thread per output element; coalesced
// writes; tables L2-resident. Dtype branch is warp-uniform.
// --------------------------------------------------------------------------
__global__ __launch_bounds__(256) void edge_out_kernel(const void* __restrict__ eiv,
                                                       float* __restrict__ out) {
    unsigned i = blockIdx.x * 256u + threadIdx.x;
    if (i >= (unsigned)NE * C) return;
    unsigned e = i / C;
    unsigned c = i - e * C;
    int s, d;
    if (g_is64) {
        const long long* ei = (const long long*)eiv;
        s = (int)ei[e];
        d = (int)ei[NE + e];
    } else {
        const int* ei = (const int*)eiv;
        s = ei[e];
        d = ei[NE + e];
    }
    out[i] = g_Asrc[s][c] + g_Adst[d][c];
}

// --------------------------------------------------------------------------
extern "C" void kernel_launch(void* const* d_in, const int* in_sizes, int n_in,
                              void* d_out, int out_size) {
    // Bind inputs by element count (robust to ordering surprises).
    const float* emb  = nullptr;
    const void*  ei   = nullptr;
    const float* Wsrc = nullptr;
    const float* Wdst = nullptr;
    const float* bf   = nullptr;
    const float* Wcls = nullptr;
    const float* bcls = nullptr;
    for (int k = 0; k < n_in; k++) {
        switch (in_sizes[k]) {
            case NN * D:     emb  = (const float*)d_in[k]; break;
            case 2 * NE:     ei   = d_in[k];               break;
            case D * D:      if (!Wsrc) Wsrc = (const float*)d_in[k];
                             else       Wdst = (const float*)d_in[k];
                             break;
            case D:          bf   = (const float*)d_in[k]; break;
            case D * C:      Wcls = (const float*)d_in[k]; break;
            case C:          bcls = (const float*)d_in[k]; break;
            default: break;
        }
    }
    float* out = (float*)d_out;

    detect_dtype_kernel<<<1, 32>>>((const long long*)ei);
    fuse_weights_kernel<<<(2 * D * C + C + 255) / 256, 256>>>(Wsrc, Wdst, bf, Wcls, bcls);
    node_proj_kernel<<<(NN + 7) / 8, dim3(32, 8)>>>(emb);
    edge_out_kernel<<<((unsigned)NE * C + 255u) / 256u, 256>>>(ei, out);
}

// round 3
// speedup vs baseline: 1.7376x; 1.7376x over previous
#include <cuda_runtime.h>
#include <cstdint>

#define NN 50000
#define NE 1600000
#define D  128
#define C  21
#define RP 32   // padded table row stride (floats) -> 128B, line-aligned

// Scratch in __device__ globals (no cudaMalloc allowed).
__device__ float g_Wc[2][D][C];          // fused Wsrc@Wcls, Wdst@Wcls
__device__ float g_cvec[C];              // b_fuse@Wcls + b_cls
__device__ __align__(128) float g_Asrc[NN][RP];  // emb @ Wc[0] + cvec
__device__ __align__(128) float g_Adst[NN][RP];  // emb @ Wc[1]
__device__ int   g_is64;
__device__ int   g_si[NE];               // int32 src indices
__device__ int   g_di[NE];               // int32 dst indices

// --------------------------------------------------------------------------
// Kernel 0: detect edge_index dtype (int32 reinterpreted as int64 is huge whp)
// --------------------------------------------------------------------------
__global__ void detect_dtype_kernel(const long long* __restrict__ ei) {
    if (threadIdx.x == 0) {
        bool ok64 = true;
        #pragma unroll
        for (int k = 0; k < 4; k++) {
            long long v = ei[k];
            if (v < 0 || v >= NN) ok64 = false;
        }
        g_is64 = ok64 ? 1 : 0;
    }
}

// --------------------------------------------------------------------------
// Kernel 0b: convert indices to int32 scratch arrays
// --------------------------------------------------------------------------
__global__ __launch_bounds__(256) void convert_idx_kernel(const void* __restrict__ eiv) {
    unsigned e = blockIdx.x * 256u + threadIdx.x;
    if (e >= NE) return;
    if (g_is64) {
        const long long* ei = (const long long*)eiv;
        g_si[e] = (int)ei[e];
        g_di[e] = (int)ei[NE + e];
    } else {
        const int* ei = (const int*)eiv;
        g_si[e] = ei[e];
        g_di[e] = ei[NE + e];
    }
}

// --------------------------------------------------------------------------
// Kernel 1: fold [D,D] fuse weights through the classifier -> [D,C] (tiny)
// --------------------------------------------------------------------------
__global__ void fuse_weights_kernel(const float* __restrict__ Wsrc,
                                    const float* __restrict__ Wdst,
                                    const float* __restrict__ bfuse,
                                    const float* __restrict__ Wcls,
                                    const float* __restrict__ bcls) {
    int i = blockIdx.x * blockDim.x + threadIdx.x;
    if (i < 2 * D * C) {
        int which = i / (D * C);
        int rem   = i - which * (D * C);
        int r = rem / C;
        int c = rem - r * C;
        const float* W = which ? Wdst : Wsrc;
        float acc = 0.f;
        #pragma unroll 16
        for (int j = 0; j < D; j++)
            acc += W[r * D + j] * Wcls[j * C + c];
        g_Wc[which][r][c] = acc;
    } else if (i < 2 * D * C + C) {
        int c = i - 2 * D * C;
        float acc = bcls[c];
        for (int j = 0; j < D; j++)
            acc += bfuse[j] * Wcls[j * C + c];
        g_cvec[c] = acc;
    }
}

// --------------------------------------------------------------------------
// Kernel 2: per-node projection tables. 32 nodes/block, 4 nodes/thread.
// Weight staging amortized over 32 nodes (was 8): 4x less L2 traffic.
// --------------------------------------------------------------------------
__global__ __launch_bounds__(256) void node_proj_kernel(const float* __restrict__ emb) {
    __shared__ float sW[2][D][C];     // 21504 B
    __shared__ float sx[32][D];       // 16384 B

    int tid = threadIdx.y * 32 + threadIdx.x;

    const float4* gW4 = (const float4*)&g_Wc[0][0][0];
    float4* sW4 = (float4*)&sW[0][0][0];
    for (int i = tid; i < 2 * D * C / 4; i += 256)
        sW4[i] = gW4[i];

    int node0 = blockIdx.x * 32;
    // stage 32 embedding rows with float4 loads (32*128 floats = 1024 float4)
    const float4* emb4 = (const float4*)emb;
    float4* sx4 = (float4*)&sx[0][0];
    for (int i = tid; i < 32 * D / 4; i += 256) {
        int n = node0 + (i >> 5);                 // i / 32 (32 float4 per row)
        sx4[i] = (n < NN) ? emb4[(size_t)n * (D / 4) + (i & 31)]
                          : make_float4(0.f, 0.f, 0.f, 0.f);
    }
    __syncthreads();

    int c = threadIdx.x;
    if (c < C) {
        float a0 = 0.f, a1 = 0.f, a2 = 0.f, a3 = 0.f;
        float b0 = 0.f, b1 = 0.f, b2 = 0.f, b3 = 0.f;
        int r = threadIdx.y;
        #pragma unroll 4
        for (int k = 0; k < D; k++) {
            float w0 = sW[0][k][c];
            float w1 = sW[1][k][c];
            float x0 = sx[r][k];
            float x1 = sx[r + 8][k];
            float x2 = sx[r + 16][k];
            float x3 = sx[r + 24][k];
            a0 += x0 * w0; b0 += x0 * w1;
            a1 += x1 * w0; b1 += x1 * w1;
            a2 += x2 * w0; b2 += x2 * w1;
            a3 += x3 * w0; b3 += x3 * w1;
        }
        float cv = g_cvec[c];
        int n0 = node0 + r;
        if (n0      < NN) { g_Asrc[n0][c]      = a0 + cv; g_Adst[n0][c]      = b0; }
        if (n0 + 8  < NN) { g_Asrc[n0 + 8][c]  = a1 + cv; g_Adst[n0 + 8][c]  = b1; }
        if (n0 + 16 < NN) { g_Asrc[n0 + 16][c] = a2 + cv; g_Adst[n0 + 16][c] = b2; }
        if (n0 + 24 < NN) { g_Asrc[n0 + 24][c] = a3 + cv; g_Adst[n0 + 24][c] = b3; }
    }
}

// --------------------------------------------------------------------------
// Kernel 3: per-edge gather+add. 4 outputs/thread, float4 stores.
// Table rows are 128B-aligned -> one L2 line per edge per table.
// --------------------------------------------------------------------------
__global__ __launch_bounds__(256) void edge_out_kernel(float4* __restrict__ out4) {
    unsigned t = blockIdx.x * 256u + threadIdx.x;
    if (t >= (unsigned)NE * C / 4) return;
    unsigned i0 = t * 4u;
    unsigned e = i0 / C;
    unsigned c = i0 - e * C;
    int s = __ldg(&g_si[e]);
    int d = __ldg(&g_di[e]);
    const float* as = g_Asrc[s];
    const float* ad = g_Adst[d];
    float4 r;
    if (c <= C - 4) {
        r.x = as[c]     + ad[c];
        r.y = as[c + 1] + ad[c + 1];
        r.z = as[c + 2] + ad[c + 2];
        r.w = as[c + 3] + ad[c + 3];
    } else {
        // straddles into edge e+1 (never past NE-1; see bounds analysis)
        int s2 = __ldg(&g_si[e + 1]);
        int d2 = __ldg(&g_di[e + 1]);
        const float* as2 = g_Asrc[s2];
        const float* ad2 = g_Adst[d2];
        float v[4];
        #pragma unroll
        for (int k = 0; k < 4; k++) {
            unsigned cc = c + k;
            v[k] = (cc < C) ? (as[cc] + ad[cc]) : (as2[cc - C] + ad2[cc - C]);
        }
        r.x = v[0]; r.y = v[1]; r.z = v[2]; r.w = v[3];
    }
    out4[t] = r;
}

// --------------------------------------------------------------------------
extern "C" void kernel_launch(void* const* d_in, const int* in_sizes, int n_in,
                              void* d_out, int out_size) {
    const float* emb  = nullptr;
    const void*  ei   = nullptr;
    const float* Wsrc = nullptr;
    const float* Wdst = nullptr;
    const float* bf   = nullptr;
    const float* Wcls = nullptr;
    const float* bcls = nullptr;
    for (int k = 0; k < n_in; k++) {
        switch (in_sizes[k]) {
            case NN * D: emb = (const float*)d_in[k]; break;
            case 2 * NE: ei  = d_in[k];               break;
            case D * D:  if (!Wsrc) Wsrc = (const float*)d_in[k];
                         else       Wdst = (const float*)d_in[k];
                         break;
            case D:      bf   = (const float*)d_in[k]; break;
            case D * C:  Wcls = (const float*)d_in[k]; break;
            case C:      bcls = (const float*)d_in[k]; break;
            default: break;
        }
    }
    float4* out4 = (float4*)d_out;

    detect_dtype_kernel<<<1, 32>>>((const long long*)ei);
    convert_idx_kernel<<<(NE + 255) / 256, 256>>>(ei);
    fuse_weights_kernel<<<(2 * D * C + C + 255) / 256, 256>>>(Wsrc, Wdst, bf, Wcls, bcls);
    node_proj_kernel<<<(NN + 31) / 32, dim3(32, 8)>>>(emb);

    unsigned nt = (unsigned)NE * C / 4;   // 8,400,000
    edge_out_kernel<<<(nt + 255u) / 256u, 256>>>(out4);
}